// round 15
// baseline (speedup 1.0000x reference)
#include <cuda_runtime.h>
#include <cuda_bf16.h>
#include <cuda_fp16.h>
#include <math.h>
#include <stdint.h>

// ---------------------------------------------------------------------------
// WeightedConformers: SchNet-style message passing + conformer readout.
//
// sm_100 BASE target (no tcgen05). Node GEMMs: mma.sync.m16n8k16 bf16 with
// split-3 error compensation (D = Ah@Bh + Ah@Bl + Al@Bh, fp32 accum).
// Edge filter: per-layer 2048-point fp16 lerp table.
//
// R13 (resubmitted R14 after infra failure): (a) persistent-B GEMM — 148
// CTAs (one wave), each holds its 128KB B-half resident in SMEM and streams
// row-blocks of A through a cp.async double buffer (per-CTA bytes halved;
// GEMMs are load-bound, not latency-bound); (b) gather emits bf16 splits
// directly (conv_act deleted; fixup_k preserves overflow exactness);
// (c) NTAB 4096->2048.
// ---------------------------------------------------------------------------

#define N_ATOMS_C 51200
#define N_EDGES_C 524288
#define D_C       256
#define NG_C      64
#define L_C       3
#define NTAB      2048
#define DMAX      8.0f
#define NMOLS     64
#define NCONFS    20
#define MOLSZ     40
#define ECAP      64
#define OVFCAP    4096

// ---------------- static device scratch (no allocations anywhere) ----------
__device__ __align__(128) float g_r[N_ATOMS_C * D_C];
__device__ __align__(128) float g_agg[N_ATOMS_C * D_C];
__device__ __align__(128) __half g_phih[N_ATOMS_C * D_C];
__device__ __align__(128) __half g_tabh[L_C][NTAB * D_C];
__device__ __align__(128) float g_cs[NMOLS * NCONFS * D_C];
__device__ __align__(128) float g_h1[NMOLS * NCONFS * 384];
__device__ __align__(128) float g_hh[NMOLS * NCONFS * 512];
__device__ __align__(128) float g_fp[NMOLS * 512];

// CSR edge lists
__device__ __align__(128) int  g_cnt[N_ATOMS_C];
__device__ __align__(128) int2 g_elist[N_ATOMS_C * ECAP];  // (a1, t bits)
__device__ int  g_ovf_cnt;
__device__ __align__(128) int4 g_ovf[OVFCAP];              // (a0, a1, t bits, -)

// bf16 split buffers (hi/lo) for GEMM A-operands
__device__ __align__(128) __nv_bfloat16 g_rs_h[N_ATOMS_C * D_C];
__device__ __align__(128) __nv_bfloat16 g_rs_l[N_ATOMS_C * D_C];
__device__ __align__(128) __nv_bfloat16 g_as_h[N_ATOMS_C * D_C];
__device__ __align__(128) __nv_bfloat16 g_as_l[N_ATOMS_C * D_C];
__device__ __align__(128) __nv_bfloat16 g_hs_h[N_ATOMS_C * D_C];
__device__ __align__(128) __nv_bfloat16 g_hs_l[N_ATOMS_C * D_C];
// transposed weight splits: [9][n*256+k] = split(W[k*256+n]); slot = l*3+{Wm,Wo1,Wo2}
__device__ __align__(128) __nv_bfloat16 g_wt_h[9 * 65536];
__device__ __align__(128) __nv_bfloat16 g_wt_l[9 * 65536];

// ---------------- small helpers --------------------------------------------
__device__ __forceinline__ float sspf(float x) {
    return fmaxf(x, 0.0f) + log1pf(expf(-fabsf(x))) - 0.69314718055994531f;
}

__device__ __forceinline__ uint32_t smem_u32(const void* p) {
    uint32_t a;
    asm("{ .reg .u64 t; cvta.to.shared.u64 t, %1; cvt.u32.u64 %0, t; }" : "=r"(a) : "l"(p));
    return a;
}

__device__ __forceinline__ uint32_t packbf(__nv_bfloat16 a, __nv_bfloat16 b) {
    __nv_bfloat162 t(a, b);
    return *reinterpret_cast<uint32_t*>(&t);
}

__device__ __forceinline__ void split2(float a, float b, uint32_t& hh, uint32_t& ll) {
    __nv_bfloat16 ha = __float2bfloat16_rn(a), hb = __float2bfloat16_rn(b);
    __nv_bfloat16 la = __float2bfloat16_rn(a - __bfloat162float(ha));
    __nv_bfloat16 lb = __float2bfloat16_rn(b - __bfloat162float(hb));
    hh = packbf(ha, hb);
    ll = packbf(la, lb);
}

__device__ __forceinline__ uint32_t swz(uint32_t off) {
    return off ^ ((off >> 3) & 0x70);  // SW128: bits[6:4] ^= bits[9:7]
}

__device__ __forceinline__ void ldmx4(uint32_t addr, uint32_t& r0, uint32_t& r1,
                                      uint32_t& r2, uint32_t& r3) {
    asm volatile("ldmatrix.sync.aligned.m8n8.x4.shared.b16 {%0, %1, %2, %3}, [%4];"
                 : "=r"(r0), "=r"(r1), "=r"(r2), "=r"(r3) : "r"(addr));
}

__device__ __forceinline__ void mma16816(float* d, const uint32_t* a, const uint32_t* b) {
    asm volatile("mma.sync.aligned.m16n8k16.row.col.f32.bf16.bf16.f32 "
                 "{%0, %1, %2, %3}, {%4, %5, %6, %7}, {%8, %9}, {%0, %1, %2, %3};"
                 : "+f"(d[0]), "+f"(d[1]), "+f"(d[2]), "+f"(d[3])
                 : "r"(a[0]), "r"(a[1]), "r"(a[2]), "r"(a[3]), "r"(b[0]), "r"(b[1]));
}

// ---------------------------------------------------------------------------
// CSR build: zero counts, then scatter (distance computed inline)
// ---------------------------------------------------------------------------
__global__ void zero_cnt_k() {
    int i = blockIdx.x * blockDim.x + threadIdx.x;
    if (i < N_ATOMS_C) g_cnt[i] = 0;
    if (i == 0) g_ovf_cnt = 0;
}

__global__ void scatter_k(const float4* __restrict__ nxyz, const int2* __restrict__ nbr) {
    int e = blockIdx.x * blockDim.x + threadIdx.x;
    int2 ab = nbr[e];
    float4 p0 = nxyz[ab.x];
    float4 p1 = nxyz[ab.y];
    float dx = p0.y - p1.y, dy = p0.z - p1.z, dz = p0.w - p1.w;
    float d = sqrtf(dx * dx + dy * dy + dz * dz + 1e-12f);
    float t = fminf(d * ((float)(NTAB - 1) / DMAX), (float)(NTAB - 1) - 0.001f);
    int pos = atomicAdd(&g_cnt[ab.x], 1);
    if (pos < ECAP) {
        g_elist[ab.x * ECAP + pos] = make_int2(ab.y, __float_as_int(t));
    } else {
        int o = atomicAdd(&g_ovf_cnt, 1);
        if (o < OVFCAP) g_ovf[o] = make_int4(ab.x, ab.y, __float_as_int(t), 0);
    }
}

// r0 = emb[z]; also emit bf16 splits
__global__ void gather_emb_k(const float4* __restrict__ emb, const int* __restrict__ z) {
    int idx = blockIdx.x * blockDim.x + threadIdx.x;  // N_ATOMS*64 float4s
    int a = idx >> 6, c = idx & 63;
    float4 v = emb[z[a] * 64 + c];
    ((float4*)g_r)[idx] = v;
    uint2 h, l;
    split2(v.x, v.y, h.x, l.x);
    split2(v.z, v.w, h.y, l.y);
    ((uint2*)g_rs_h)[idx] = h;
    ((uint2*)g_rs_l)[idx] = l;
}

// weights -> transposed bf16 splits. slot = l*3 + {0:Wm,1:Wo1,2:Wo2}
__global__ void conv_w_k(const float* __restrict__ Wm, const float* __restrict__ Wo1,
                         const float* __restrict__ Wo2) {
    int idx = blockIdx.x * blockDim.x + threadIdx.x;  // 9*65536
    int slot = idx >> 16, rem = idx & 65535;
    int k = rem >> 8, n = rem & 255;
    int l = slot / 3, j = slot - l * 3;
    const float* W = (j == 0 ? Wm : (j == 1 ? Wo1 : Wo2)) + l * 65536;
    float v = W[k * 256 + n];
    __nv_bfloat16 h = __float2bfloat16_rn(v);
    __nv_bfloat16 lo = __float2bfloat16_rn(v - __bfloat162float(h));
    g_wt_h[slot * 65536 + n * 256 + k] = h;
    g_wt_l[slot * 65536 + n * 256 + k] = lo;
}

// ---------------------------------------------------------------------------
// Filter table, 32 rows/block, fp16 output. Activations transposed in shared
// with a 36-float padded row (16B-aligned float4 broadcast loads).
// ---------------------------------------------------------------------------
__global__ __launch_bounds__(256) void build_tab_k(
    const float* __restrict__ Wf1, const float* __restrict__ bf1,
    const float* __restrict__ Wf2, const float* __restrict__ bf2) {
    __shared__ float sg2[NG_C * 36];   // [j][ri], row stride 36
    __shared__ float sh2[D_C * 36];    // [k][ri], row stride 36
    int i0 = blockIdx.x * 32, l = blockIdx.y, t = threadIdx.x;

    for (int u = t; u < 32 * NG_C; u += 256) {
        int j = u >> 5, ri = u & 31;
        float dv = (float)(i0 + ri) * (DMAX / (float)(NTAB - 1));
        float mu = (float)j * (5.0f / 63.0f);
        float x = (dv - mu) * (63.0f / 5.0f);
        sg2[j * 36 + ri] = expf(-0.5f * x * x);
    }
    __syncthreads();

    float acc[32];
    float b1v = bf1[l * D_C + t];
#pragma unroll
    for (int ri = 0; ri < 32; ri++) acc[ri] = b1v;
    for (int j = 0; j < NG_C; j++) {
        float w = Wf1[(l * NG_C + j) * D_C + t];
        const float4* s = (const float4*)(sg2 + j * 36);
#pragma unroll
        for (int q = 0; q < 8; q++) {
            float4 sv = s[q];
            acc[q * 4 + 0] = fmaf(sv.x, w, acc[q * 4 + 0]);
            acc[q * 4 + 1] = fmaf(sv.y, w, acc[q * 4 + 1]);
            acc[q * 4 + 2] = fmaf(sv.z, w, acc[q * 4 + 2]);
            acc[q * 4 + 3] = fmaf(sv.w, w, acc[q * 4 + 3]);
        }
    }
    {
        float4* dst = (float4*)(sh2 + t * 36);
#pragma unroll
        for (int q = 0; q < 8; q++)
            dst[q] = make_float4(sspf(acc[q * 4 + 0]), sspf(acc[q * 4 + 1]),
                                 sspf(acc[q * 4 + 2]), sspf(acc[q * 4 + 3]));
    }
    __syncthreads();

    float b2v = bf2[l * D_C + t];
#pragma unroll
    for (int ri = 0; ri < 32; ri++) acc[ri] = b2v;
    for (int k = 0; k < D_C; k++) {
        float w = Wf2[(l * D_C + k) * D_C + t];
        const float4* s = (const float4*)(sh2 + k * 36);
#pragma unroll
        for (int q = 0; q < 8; q++) {
            float4 sv = s[q];
            acc[q * 4 + 0] = fmaf(sv.x, w, acc[q * 4 + 0]);
            acc[q * 4 + 1] = fmaf(sv.y, w, acc[q * 4 + 1]);
            acc[q * 4 + 2] = fmaf(sv.z, w, acc[q * 4 + 2]);
            acc[q * 4 + 3] = fmaf(sv.w, w, acc[q * 4 + 3]);
        }
    }
#pragma unroll
    for (int ri = 0; ri < 32; ri++)
        g_tabh[l][(i0 + ri) * D_C + t] = __float2half_rn(acc[ri]);
}

// ---------------------------------------------------------------------------
// CSR gather (fp16 table/phi): one warp per atom, lane owns 8 channels.
// Emits fp32 agg AND bf16 hi/lo splits directly (conv_act fused away).
// ---------------------------------------------------------------------------
__global__ __launch_bounds__(256) void gather_k(int l) {
    int a = blockIdx.x * 8 + (threadIdx.x >> 5);
    int lane = threadIdx.x & 31;
    int cnt = g_cnt[a];
    if (cnt > ECAP) cnt = ECAP;
    const int2* lst = g_elist + a * ECAP;
    const uint4* tabl = (const uint4*)g_tabh[l];  // 32 uint4 per 256-ch row
    const uint4* phih = (const uint4*)g_phih;
    float acc[8];
#pragma unroll
    for (int q = 0; q < 8; q++) acc[q] = 0.f;
#pragma unroll 2
    for (int i = 0; i < cnt; i++) {
        int2 rec = lst[i];
        float t = __int_as_float(rec.y);
        int i0 = (int)t;
        float f = t - (float)i0;
        uint4 xa = tabl[(size_t)i0 * 32 + lane];
        uint4 xb = tabl[(size_t)(i0 + 1) * 32 + lane];
        uint4 pp = phih[(size_t)rec.x * 32 + lane];
        const __half2* ha = (const __half2*)&xa;
        const __half2* hb = (const __half2*)&xb;
        const __half2* hp = (const __half2*)&pp;
#pragma unroll
        for (int q = 0; q < 4; q++) {
            float2 a0 = __half22float2(ha[q]);
            float2 b0 = __half22float2(hb[q]);
            float2 p0 = __half22float2(hp[q]);
            float f0 = fmaf(f, b0.x - a0.x, a0.x);
            float f1 = fmaf(f, b0.y - a0.y, a0.y);
            acc[q * 2 + 0] = fmaf(f0, p0.x, acc[q * 2 + 0]);
            acc[q * 2 + 1] = fmaf(f1, p0.y, acc[q * 2 + 1]);
        }
    }
    float4* ag = (float4*)(g_agg + (size_t)a * D_C) + lane * 2;
    ag[0] = make_float4(acc[0], acc[1], acc[2], acc[3]);
    ag[1] = make_float4(acc[4], acc[5], acc[6], acc[7]);
    uint4 h, l2;
    split2(acc[0], acc[1], h.x, l2.x);
    split2(acc[2], acc[3], h.y, l2.y);
    split2(acc[4], acc[5], h.z, l2.z);
    split2(acc[6], acc[7], h.w, l2.w);
    ((uint4*)(g_as_h + (size_t)a * D_C))[lane] = h;
    ((uint4*)(g_as_l + (size_t)a * D_C))[lane] = l2;
}

// Overflow edges (expected count 0): atomic add on top of gather's stores.
__global__ void ovf_k(int l) {
    int w = threadIdx.x >> 5, lane = threadIdx.x & 31;
    int n = g_ovf_cnt;
    if (n > OVFCAP) n = OVFCAP;
    const uint4* tabl = (const uint4*)g_tabh[l];
    const uint4* phih = (const uint4*)g_phih;
    for (int i = w; i < n; i += 8) {
        int4 rec = g_ovf[i];
        float t = __int_as_float(rec.z);
        int i0 = (int)t;
        float f = t - (float)i0;
        uint4 xa = tabl[(size_t)i0 * 32 + lane];
        uint4 xb = tabl[(size_t)(i0 + 1) * 32 + lane];
        uint4 pp = phih[(size_t)rec.y * 32 + lane];
        const __half2* ha = (const __half2*)&xa;
        const __half2* hb = (const __half2*)&xb;
        const __half2* hp = (const __half2*)&pp;
        float v[8];
#pragma unroll
        for (int q = 0; q < 4; q++) {
            float2 a0 = __half22float2(ha[q]);
            float2 b0 = __half22float2(hb[q]);
            float2 p0 = __half22float2(hp[q]);
            v[q * 2 + 0] = fmaf(f, b0.x - a0.x, a0.x) * p0.x;
            v[q * 2 + 1] = fmaf(f, b0.y - a0.y, a0.y) * p0.y;
        }
        float* ag = g_agg + (size_t)rec.x * D_C + lane * 8;
        asm volatile("red.global.add.v4.f32 [%0], {%1, %2, %3, %4};"
                     :: "l"(ag), "f"(v[0]), "f"(v[1]), "f"(v[2]), "f"(v[3]) : "memory");
        asm volatile("red.global.add.v4.f32 [%0], {%1, %2, %3, %4};"
                     :: "l"(ag + 4), "f"(v[4]), "f"(v[5]), "f"(v[6]), "f"(v[7]) : "memory");
    }
}

// Re-split atoms touched by overflow (no-op when g_ovf_cnt == 0).
__global__ void fixup_k() {
    int w = threadIdx.x >> 5, lane = threadIdx.x & 31;
    int n = g_ovf_cnt;
    if (n > OVFCAP) n = OVFCAP;
    for (int i = w; i < n; i += 8) {
        int a = g_ovf[i].x;
        const float4* ar = (const float4*)(g_agg + (size_t)a * D_C);
        float4 v0 = ar[lane * 2], v1 = ar[lane * 2 + 1];
        uint4 h, l2;
        split2(v0.x, v0.y, h.x, l2.x);
        split2(v0.z, v0.w, h.y, l2.y);
        split2(v1.x, v1.y, h.z, l2.z);
        split2(v1.z, v1.w, h.w, l2.w);
        ((uint4*)(g_as_h + (size_t)a * D_C))[lane] = h;
        ((uint4*)(g_as_l + (size_t)a * D_C))[lane] = l2;
    }
}

// ---------------------------------------------------------------------------
// Persistent-B mma.sync bf16 split-3 GEMM: C[51200,256] = A@W (+epilogue).
//   Grid (74, 2) = 148 CTAs (one wave). Each CTA loads its 128KB B column
//   half once into SMEM (4 chunk-tiles x 16KB x hi/lo) and streams row
//   blocks of A through a cp.async double buffer (2 x 32KB).
//   SMEM: B 128KB + A stages 64KB = 192KB, 1 CTA/SM.
// MODE 0: PhiH = half(D + bias)                (phi, fp16 out)
// MODE 1: splits(ssp(D + bias)) -> Oh/Ol       (hidden)
// MODE 2: Cout = Cin + D + bias, also splits   (residual)
// ---------------------------------------------------------------------------
#define SMEM_DYN 196608  // 131072 (B) + 2*32768 (A stages)

__device__ __forceinline__ void cp_tile(const __nv_bfloat16* __restrict__ src,
                                        int k0, uint32_t dst, int t) {
#pragma unroll
    for (int u = t; u < 1024; u += 256) {
        int r = u >> 3, c = u & 7;
        const void* g = src + (size_t)r * 256 + k0 + c * 8;
        uint32_t d = dst + swz((uint32_t)(r * 128 + c * 16));
        asm volatile("cp.async.cg.shared.global [%0], [%1], 16;" :: "r"(d), "l"(g));
    }
}

template <int MODE>
__global__ __launch_bounds__(256) void bmma_k(
    const __nv_bfloat16* __restrict__ Ah, const __nv_bfloat16* __restrict__ Al,
    const __nv_bfloat16* __restrict__ Bh, const __nv_bfloat16* __restrict__ Bl,
    const float* __restrict__ bias, const float* __restrict__ Cin,
    float* __restrict__ Cout, __nv_bfloat16* __restrict__ Oh,
    __nv_bfloat16* __restrict__ Ol, __half* __restrict__ PhiH) {
    extern __shared__ char smem[];
    const int t = threadIdx.x, wid = t >> 5, lane = t & 31;
    const int wm = wid & 1, wn = wid >> 1;  // warp grid 2(M) x 4(N)
    const int n0 = blockIdx.y * 128;
    const int bx = blockIdx.x;  // 0..73

    const uint32_t sb = smem_u32(smem);
    const __nv_bfloat16* Bhb = Bh + (size_t)n0 * 256;
    const __nv_bfloat16* Blb = Bl + (size_t)n0 * 256;

    // Resident B: chunk c hi at sb + c*16384, lo at sb + 65536 + c*16384.
#pragma unroll
    for (int c = 0; c < 4; c++) {
        cp_tile(Bhb, c * 64, sb + (uint32_t)c * 16384, t);
        cp_tile(Blb, c * 64, sb + 65536 + (uint32_t)c * 16384, t);
    }
    asm volatile("cp.async.commit_group;" ::: "memory");

    const int nblk = (400 - bx + 73) / 74;  // 5 or 6 row blocks
    const int total = nblk * 4;

    auto issueA = [&](int g) {
        int m0 = (bx + (g >> 2) * 74) * 128;
        int k0 = (g & 3) * 64;
        uint32_t st = sb + 131072 + (uint32_t)(g & 1) * 32768;
        cp_tile(Ah + (size_t)m0 * 256, k0, st, t);
        cp_tile(Al + (size_t)m0 * 256, k0, st + 16384, t);
        asm volatile("cp.async.commit_group;" ::: "memory");
    };

    issueA(0);

    const int lrow = lane & 15;
    const int lkb = (lane >> 4) << 4;
    const int qr = lane >> 2, qc = (lane & 3) * 2;

    float acc[4][4][4];

    for (int g = 0; g < total; g++) {
        if ((g & 3) == 0) {
#pragma unroll
            for (int i = 0; i < 4; i++)
#pragma unroll
                for (int j = 0; j < 4; j++)
#pragma unroll
                    for (int q = 0; q < 4; q++) acc[i][j][q] = 0.f;
        }
        if (g + 1 < total) {
            issueA(g + 1);
            asm volatile("cp.async.wait_group 1;" ::: "memory");
        } else {
            asm volatile("cp.async.wait_group 0;" ::: "memory");
        }
        __syncthreads();
        const int c = g & 3;
        const uint32_t sbh = sb + (uint32_t)c * 16384;
        const uint32_t sbl = sbh + 65536;
        const uint32_t sa = sb + 131072 + (uint32_t)(g & 1) * 32768;
#pragma unroll
        for (int k16 = 0; k16 < 4; k16++) {
            int kb = k16 * 32 + lkb;
            uint32_t bh[4][2], bl[4][2];
#pragma unroll
            for (int p = 0; p < 2; p++) {
                uint32_t off = swz((uint32_t)((wn * 32 + p * 16 + lrow) * 128 + kb));
                uint32_t r0, r1, r2, r3;
                ldmx4(sbh + off, r0, r1, r2, r3);
                bh[p * 2 + 0][0] = r0; bh[p * 2 + 1][0] = r1;
                bh[p * 2 + 0][1] = r2; bh[p * 2 + 1][1] = r3;
                ldmx4(sbl + off, r0, r1, r2, r3);
                bl[p * 2 + 0][0] = r0; bl[p * 2 + 1][0] = r1;
                bl[p * 2 + 0][1] = r2; bl[p * 2 + 1][1] = r3;
            }
#pragma unroll
            for (int mt = 0; mt < 4; mt++) {
                uint32_t off = swz((uint32_t)((wm * 64 + mt * 16 + lrow) * 128 + kb));
                uint32_t ah[4], al[4];
                ldmx4(sa + off, ah[0], ah[1], ah[2], ah[3]);
                ldmx4(sa + 16384 + off, al[0], al[1], al[2], al[3]);
#pragma unroll
                for (int nt = 0; nt < 4; nt++) {
                    mma16816(acc[mt][nt], ah, bh[nt]);
                    mma16816(acc[mt][nt], ah, bl[nt]);
                    mma16816(acc[mt][nt], al, bh[nt]);
                }
            }
        }
        __syncthreads();

        if ((g & 3) == 3) {
            int m0 = (bx + (g >> 2) * 74) * 128;
#pragma unroll
            for (int mt = 0; mt < 4; mt++) {
#pragma unroll
                for (int half = 0; half < 2; half++) {
                    int r = m0 + wm * 64 + mt * 16 + qr + half * 8;
#pragma unroll
                    for (int nt = 0; nt < 4; nt++) {
                        int cc = n0 + wn * 32 + nt * 8 + qc;
                        float v0 = acc[mt][nt][half * 2 + 0] + bias[cc];
                        float v1 = acc[mt][nt][half * 2 + 1] + bias[cc + 1];
                        if (MODE == 0) {
                            __half2 hv = __floats2half2_rn(v0, v1);
                            *(uint32_t*)(PhiH + (size_t)r * 256 + cc) =
                                *reinterpret_cast<uint32_t*>(&hv);
                        }
                        if (MODE == 1) { v0 = sspf(v0); v1 = sspf(v1); }
                        if (MODE == 2) {
                            float2 ci = *(const float2*)(Cin + (size_t)r * 256 + cc);
                            v0 += ci.x; v1 += ci.y;
                            *(float2*)(Cout + (size_t)r * 256 + cc) = make_float2(v0, v1);
                        }
                        if (MODE != 0) {
                            uint32_t h, l;
                            split2(v0, v1, h, l);
                            *(uint32_t*)(Oh + (size_t)r * 256 + cc) = h;
                            *(uint32_t*)(Ol + (size_t)r * 256 + cc) = l;
                        }
                    }
                }
            }
        }
    }
}

// ---------------------------------------------------------------------------
// Readout tail (tiny)
// ---------------------------------------------------------------------------
__global__ void conf_sum_k() {
    int row = blockIdx.x, t = threadIdx.x;
    float s = 0.f;
#pragma unroll
    for (int i = 0; i < MOLSZ; i++) s += g_r[(row * MOLSZ + i) * D_C + t];
    g_cs[row * D_C + t] = s;
}

__global__ void mlp1_k(const float* __restrict__ mW1, const float* __restrict__ mb1) {
    __shared__ float s[D_C];
    int row = blockIdx.x, t = threadIdx.x;
    if (t < D_C) s[t] = g_cs[row * D_C + t];
    __syncthreads();
    float a = mb1[t];
    for (int k = 0; k < D_C; k++) a += s[k] * mW1[k * 384 + t];
    g_h1[row * 384 + t] = sspf(a);
}

__global__ void mlp2_k(const float* __restrict__ mW2, const float* __restrict__ mb2) {
    __shared__ float s[384];
    int row = blockIdx.x, t = threadIdx.x;
    if (t < 384) s[t] = g_h1[row * 384 + t];
    __syncthreads();
    float a = mb2[t];
    for (int k = 0; k < 384; k++) a += s[k] * mW2[k * 512 + t];
    g_hh[row * 512 + t] = a;
}

__global__ void fp_k(const float* __restrict__ w) {
    int m = blockIdx.x, t = threadIdx.x;
    float a = 0.f;
#pragma unroll
    for (int c = 0; c < NCONFS; c++)
        a += w[m * NCONFS + c] * g_hh[(m * NCONFS + c) * 512 + t];
    g_fp[m * 512 + t] = a;
}

__global__ void readout_k(const float* __restrict__ rW1, const float* __restrict__ rb1,
                          const float* __restrict__ rW2, const float* __restrict__ rb2,
                          float* __restrict__ out) {
    __shared__ float s[512];
    __shared__ float red[256];
    int m = blockIdx.x, t = threadIdx.x;
    s[t] = g_fp[m * 512 + t];
    s[t + 256] = g_fp[m * 512 + 256 + t];
    __syncthreads();
    float a = rb1[t];
    for (int j = 0; j < 512; j++) a += s[j] * rW1[j * D_C + t];
    red[t] = sspf(a) * rW2[t];
    __syncthreads();
    for (int st = 128; st > 0; st >>= 1) {
        if (t < st) red[t] += red[t + st];
        __syncthreads();
    }
    if (t == 0) out[m] = red[0] + rb2[0];
}

// ---------------------------------------------------------------------------
extern "C" void kernel_launch(void* const* d_in, const int* in_sizes, int n_in,
                              void* d_out, int out_size) {
    const float* nxyz    = (const float*)d_in[0];
    const float* weights = (const float*)d_in[1];
    const float* emb     = (const float*)d_in[2];
    const float* Wm      = (const float*)d_in[3];
    const float* bm      = (const float*)d_in[4];
    const float* Wf1     = (const float*)d_in[5];
    const float* bf1     = (const float*)d_in[6];
    const float* Wf2     = (const float*)d_in[7];
    const float* bf2     = (const float*)d_in[8];
    const float* Wo1     = (const float*)d_in[9];
    const float* bo1     = (const float*)d_in[10];
    const float* Wo2     = (const float*)d_in[11];
    const float* bo2     = (const float*)d_in[12];
    const float* mW1     = (const float*)d_in[13];
    const float* mb1     = (const float*)d_in[14];
    const float* mW2     = (const float*)d_in[15];
    const float* mb2     = (const float*)d_in[16];
    const float* rW1     = (const float*)d_in[17];
    const float* rb1     = (const float*)d_in[18];
    const float* rW2     = (const float*)d_in[19];
    const float* rb2     = (const float*)d_in[20];
    const int*   z       = (const int*)d_in[21];
    const int2*  nbr     = (const int2*)d_in[22];

    float *p_r;
    __half *p_phih;
    __nv_bfloat16 *p_rsh, *p_rsl, *p_ash, *p_asl, *p_hsh, *p_hsl, *p_wth, *p_wtl;
    cudaGetSymbolAddress((void**)&p_r, g_r);
    cudaGetSymbolAddress((void**)&p_phih, g_phih);
    cudaGetSymbolAddress((void**)&p_rsh, g_rs_h);
    cudaGetSymbolAddress((void**)&p_rsl, g_rs_l);
    cudaGetSymbolAddress((void**)&p_ash, g_as_h);
    cudaGetSymbolAddress((void**)&p_asl, g_as_l);
    cudaGetSymbolAddress((void**)&p_hsh, g_hs_h);
    cudaGetSymbolAddress((void**)&p_hsl, g_hs_l);
    cudaGetSymbolAddress((void**)&p_wth, g_wt_h);
    cudaGetSymbolAddress((void**)&p_wtl, g_wt_l);

    cudaFuncSetAttribute(bmma_k<0>, cudaFuncAttributeMaxDynamicSharedMemorySize, SMEM_DYN);
    cudaFuncSetAttribute(bmma_k<1>, cudaFuncAttributeMaxDynamicSharedMemorySize, SMEM_DYN);
    cudaFuncSetAttribute(bmma_k<2>, cudaFuncAttributeMaxDynamicSharedMemorySize, SMEM_DYN);

    zero_cnt_k<<<(N_ATOMS_C + 255) / 256, 256>>>();
    scatter_k<<<N_EDGES_C / 256, 256>>>((const float4*)nxyz, nbr);
    gather_emb_k<<<(N_ATOMS_C * 64) / 256, 256>>>((const float4*)emb, z);
    conv_w_k<<<(9 * 65536) / 256, 256>>>(Wm, Wo1, Wo2);
    build_tab_k<<<dim3(NTAB / 32, L_C), 256>>>(Wf1, bf1, Wf2, bf2);

    dim3 gg(74, 2);  // persistent: one wave of 148 CTAs
    for (int l = 0; l < L_C; l++) {
        int s0 = (l * 3 + 0) * 65536, s1 = (l * 3 + 1) * 65536, s2 = (l * 3 + 2) * 65536;
        bmma_k<0><<<gg, 256, SMEM_DYN>>>(p_rsh, p_rsl, p_wth + s0, p_wtl + s0,
                                         bm + l * D_C, nullptr, nullptr, nullptr, nullptr,
                                         p_phih);
        gather_k<<<N_ATOMS_C / 8, 256>>>(l);
        ovf_k<<<1, 256>>>(l);
        fixup_k<<<1, 256>>>();
        bmma_k<1><<<gg, 256, SMEM_DYN>>>(p_ash, p_asl, p_wth + s1, p_wtl + s1,
                                         bo1 + l * D_C, nullptr, nullptr, p_hsh, p_hsl,
                                         nullptr);
        bmma_k<2><<<gg, 256, SMEM_DYN>>>(p_hsh, p_hsl, p_wth + s2, p_wtl + s2,
                                         bo2 + l * D_C, p_r, p_r, p_rsh, p_rsl,
                                         nullptr);
    }

    conf_sum_k<<<NMOLS * NCONFS, 256>>>();
    mlp1_k<<<NMOLS * NCONFS, 384>>>(mW1, mb1);
    mlp2_k<<<NMOLS * NCONFS, 512>>>(mW2, mb2);
    fp_k<<<NMOLS, 512>>>(weights);
    readout_k<<<NMOLS, 256>>>(rW1, rb1, rW2, rb2, (float*)d_out);
}

// round 17
// speedup vs baseline: 1.3223x; 1.3223x over previous
#include <cuda_runtime.h>
#include <cuda_bf16.h>
#include <cuda_fp16.h>
#include <math.h>
#include <stdint.h>

// ---------------------------------------------------------------------------
// WeightedConformers: SchNet-style message passing + conformer readout.
//
// sm_100 BASE target (no tcgen05). Node GEMMs: mma.sync.m16n8k16 bf16 with
// split-3 error compensation (D = Ah@Bh + Ah@Bl + Al@Bh, fp32 accum).
// Edge filter: per-layer 2048-point fp16 lerp table.
//
// R15 (resubmitted R16 after infra failure): persistent-B GEMM REVERTED (it
// serialized the chip: 148 CTAs x 1/SM had no latency-hiding concurrency;
// regressed 1322->1696). Back to the proven R12 bmma: grid (400,2), 2x64KB
// cp.async double buffer. Kept from R13: gather-fused bf16 splits (conv_act
// deleted; all GEMM modes use the bf16 path) and NTAB=2048 (accuracy cost
// measured at ~2.1e-5).
// ---------------------------------------------------------------------------

#define N_ATOMS_C 51200
#define N_EDGES_C 524288
#define D_C       256
#define NG_C      64
#define L_C       3
#define NTAB      2048
#define DMAX      8.0f
#define NMOLS     64
#define NCONFS    20
#define MOLSZ     40
#define ECAP      64
#define OVFCAP    4096

// ---------------- static device scratch (no allocations anywhere) ----------
__device__ __align__(128) float g_r[N_ATOMS_C * D_C];
__device__ __align__(128) float g_agg[N_ATOMS_C * D_C];
__device__ __align__(128) __half g_phih[N_ATOMS_C * D_C];
__device__ __align__(128) __half g_tabh[L_C][NTAB * D_C];
__device__ __align__(128) float g_cs[NMOLS * NCONFS * D_C];
__device__ __align__(128) float g_h1[NMOLS * NCONFS * 384];
__device__ __align__(128) float g_hh[NMOLS * NCONFS * 512];
__device__ __align__(128) float g_fp[NMOLS * 512];

// CSR edge lists
__device__ __align__(128) int  g_cnt[N_ATOMS_C];
__device__ __align__(128) int2 g_elist[N_ATOMS_C * ECAP];  // (a1, t bits)
__device__ int  g_ovf_cnt;
__device__ __align__(128) int4 g_ovf[OVFCAP];              // (a0, a1, t bits, -)

// bf16 split buffers (hi/lo) for GEMM A-operands
__device__ __align__(128) __nv_bfloat16 g_rs_h[N_ATOMS_C * D_C];
__device__ __align__(128) __nv_bfloat16 g_rs_l[N_ATOMS_C * D_C];
__device__ __align__(128) __nv_bfloat16 g_as_h[N_ATOMS_C * D_C];
__device__ __align__(128) __nv_bfloat16 g_as_l[N_ATOMS_C * D_C];
__device__ __align__(128) __nv_bfloat16 g_hs_h[N_ATOMS_C * D_C];
__device__ __align__(128) __nv_bfloat16 g_hs_l[N_ATOMS_C * D_C];
// transposed weight splits: [9][n*256+k] = split(W[k*256+n]); slot = l*3+{Wm,Wo1,Wo2}
__device__ __align__(128) __nv_bfloat16 g_wt_h[9 * 65536];
__device__ __align__(128) __nv_bfloat16 g_wt_l[9 * 65536];

// ---------------- small helpers --------------------------------------------
__device__ __forceinline__ float sspf(float x) {
    return fmaxf(x, 0.0f) + log1pf(expf(-fabsf(x))) - 0.69314718055994531f;
}

__device__ __forceinline__ uint32_t smem_u32(const void* p) {
    uint32_t a;
    asm("{ .reg .u64 t; cvta.to.shared.u64 t, %1; cvt.u32.u64 %0, t; }" : "=r"(a) : "l"(p));
    return a;
}

__device__ __forceinline__ uint32_t packbf(__nv_bfloat16 a, __nv_bfloat16 b) {
    __nv_bfloat162 t(a, b);
    return *reinterpret_cast<uint32_t*>(&t);
}

__device__ __forceinline__ void split2(float a, float b, uint32_t& hh, uint32_t& ll) {
    __nv_bfloat16 ha = __float2bfloat16_rn(a), hb = __float2bfloat16_rn(b);
    __nv_bfloat16 la = __float2bfloat16_rn(a - __bfloat162float(ha));
    __nv_bfloat16 lb = __float2bfloat16_rn(b - __bfloat162float(hb));
    hh = packbf(ha, hb);
    ll = packbf(la, lb);
}

__device__ __forceinline__ uint32_t swz(uint32_t off) {
    return off ^ ((off >> 3) & 0x70);  // SW128: bits[6:4] ^= bits[9:7]
}

__device__ __forceinline__ void ldmx4(uint32_t addr, uint32_t& r0, uint32_t& r1,
                                      uint32_t& r2, uint32_t& r3) {
    asm volatile("ldmatrix.sync.aligned.m8n8.x4.shared.b16 {%0, %1, %2, %3}, [%4];"
                 : "=r"(r0), "=r"(r1), "=r"(r2), "=r"(r3) : "r"(addr));
}

__device__ __forceinline__ void mma16816(float* d, const uint32_t* a, const uint32_t* b) {
    asm volatile("mma.sync.aligned.m16n8k16.row.col.f32.bf16.bf16.f32 "
                 "{%0, %1, %2, %3}, {%4, %5, %6, %7}, {%8, %9}, {%0, %1, %2, %3};"
                 : "+f"(d[0]), "+f"(d[1]), "+f"(d[2]), "+f"(d[3])
                 : "r"(a[0]), "r"(a[1]), "r"(a[2]), "r"(a[3]), "r"(b[0]), "r"(b[1]));
}

// ---------------------------------------------------------------------------
// CSR build: zero counts, then scatter (distance computed inline)
// ---------------------------------------------------------------------------
__global__ void zero_cnt_k() {
    int i = blockIdx.x * blockDim.x + threadIdx.x;
    if (i < N_ATOMS_C) g_cnt[i] = 0;
    if (i == 0) g_ovf_cnt = 0;
}

__global__ void scatter_k(const float4* __restrict__ nxyz, const int2* __restrict__ nbr) {
    int e = blockIdx.x * blockDim.x + threadIdx.x;
    int2 ab = nbr[e];
    float4 p0 = nxyz[ab.x];
    float4 p1 = nxyz[ab.y];
    float dx = p0.y - p1.y, dy = p0.z - p1.z, dz = p0.w - p1.w;
    float d = sqrtf(dx * dx + dy * dy + dz * dz + 1e-12f);
    float t = fminf(d * ((float)(NTAB - 1) / DMAX), (float)(NTAB - 1) - 0.001f);
    int pos = atomicAdd(&g_cnt[ab.x], 1);
    if (pos < ECAP) {
        g_elist[ab.x * ECAP + pos] = make_int2(ab.y, __float_as_int(t));
    } else {
        int o = atomicAdd(&g_ovf_cnt, 1);
        if (o < OVFCAP) g_ovf[o] = make_int4(ab.x, ab.y, __float_as_int(t), 0);
    }
}

// r0 = emb[z]; also emit bf16 splits
__global__ void gather_emb_k(const float4* __restrict__ emb, const int* __restrict__ z) {
    int idx = blockIdx.x * blockDim.x + threadIdx.x;  // N_ATOMS*64 float4s
    int a = idx >> 6, c = idx & 63;
    float4 v = emb[z[a] * 64 + c];
    ((float4*)g_r)[idx] = v;
    uint2 h, l;
    split2(v.x, v.y, h.x, l.x);
    split2(v.z, v.w, h.y, l.y);
    ((uint2*)g_rs_h)[idx] = h;
    ((uint2*)g_rs_l)[idx] = l;
}

// weights -> transposed bf16 splits. slot = l*3 + {0:Wm,1:Wo1,2:Wo2}
__global__ void conv_w_k(const float* __restrict__ Wm, const float* __restrict__ Wo1,
                         const float* __restrict__ Wo2) {
    int idx = blockIdx.x * blockDim.x + threadIdx.x;  // 9*65536
    int slot = idx >> 16, rem = idx & 65535;
    int k = rem >> 8, n = rem & 255;
    int l = slot / 3, j = slot - l * 3;
    const float* W = (j == 0 ? Wm : (j == 1 ? Wo1 : Wo2)) + l * 65536;
    float v = W[k * 256 + n];
    __nv_bfloat16 h = __float2bfloat16_rn(v);
    __nv_bfloat16 lo = __float2bfloat16_rn(v - __bfloat162float(h));
    g_wt_h[slot * 65536 + n * 256 + k] = h;
    g_wt_l[slot * 65536 + n * 256 + k] = lo;
}

// ---------------------------------------------------------------------------
// Filter table, 32 rows/block, fp16 output. Activations transposed in shared
// with a 36-float padded row (16B-aligned float4 broadcast loads).
// ---------------------------------------------------------------------------
__global__ __launch_bounds__(256) void build_tab_k(
    const float* __restrict__ Wf1, const float* __restrict__ bf1,
    const float* __restrict__ Wf2, const float* __restrict__ bf2) {
    __shared__ float sg2[NG_C * 36];   // [j][ri], row stride 36
    __shared__ float sh2[D_C * 36];    // [k][ri], row stride 36
    int i0 = blockIdx.x * 32, l = blockIdx.y, t = threadIdx.x;

    for (int u = t; u < 32 * NG_C; u += 256) {
        int j = u >> 5, ri = u & 31;
        float dv = (float)(i0 + ri) * (DMAX / (float)(NTAB - 1));
        float mu = (float)j * (5.0f / 63.0f);
        float x = (dv - mu) * (63.0f / 5.0f);
        sg2[j * 36 + ri] = expf(-0.5f * x * x);
    }
    __syncthreads();

    float acc[32];
    float b1v = bf1[l * D_C + t];
#pragma unroll
    for (int ri = 0; ri < 32; ri++) acc[ri] = b1v;
    for (int j = 0; j < NG_C; j++) {
        float w = Wf1[(l * NG_C + j) * D_C + t];
        const float4* s = (const float4*)(sg2 + j * 36);
#pragma unroll
        for (int q = 0; q < 8; q++) {
            float4 sv = s[q];
            acc[q * 4 + 0] = fmaf(sv.x, w, acc[q * 4 + 0]);
            acc[q * 4 + 1] = fmaf(sv.y, w, acc[q * 4 + 1]);
            acc[q * 4 + 2] = fmaf(sv.z, w, acc[q * 4 + 2]);
            acc[q * 4 + 3] = fmaf(sv.w, w, acc[q * 4 + 3]);
        }
    }
    {
        float4* dst = (float4*)(sh2 + t * 36);
#pragma unroll
        for (int q = 0; q < 8; q++)
            dst[q] = make_float4(sspf(acc[q * 4 + 0]), sspf(acc[q * 4 + 1]),
                                 sspf(acc[q * 4 + 2]), sspf(acc[q * 4 + 3]));
    }
    __syncthreads();

    float b2v = bf2[l * D_C + t];
#pragma unroll
    for (int ri = 0; ri < 32; ri++) acc[ri] = b2v;
    for (int k = 0; k < D_C; k++) {
        float w = Wf2[(l * D_C + k) * D_C + t];
        const float4* s = (const float4*)(sh2 + k * 36);
#pragma unroll
        for (int q = 0; q < 8; q++) {
            float4 sv = s[q];
            acc[q * 4 + 0] = fmaf(sv.x, w, acc[q * 4 + 0]);
            acc[q * 4 + 1] = fmaf(sv.y, w, acc[q * 4 + 1]);
            acc[q * 4 + 2] = fmaf(sv.z, w, acc[q * 4 + 2]);
            acc[q * 4 + 3] = fmaf(sv.w, w, acc[q * 4 + 3]);
        }
    }
#pragma unroll
    for (int ri = 0; ri < 32; ri++)
        g_tabh[l][(i0 + ri) * D_C + t] = __float2half_rn(acc[ri]);
}

// ---------------------------------------------------------------------------
// CSR gather (fp16 table/phi): one warp per atom, lane owns 8 channels.
// Emits fp32 agg AND bf16 hi/lo splits directly (conv_act fused away).
// ---------------------------------------------------------------------------
__global__ __launch_bounds__(256) void gather_k(int l) {
    int a = blockIdx.x * 8 + (threadIdx.x >> 5);
    int lane = threadIdx.x & 31;
    int cnt = g_cnt[a];
    if (cnt > ECAP) cnt = ECAP;
    const int2* lst = g_elist + a * ECAP;
    const uint4* tabl = (const uint4*)g_tabh[l];  // 32 uint4 per 256-ch row
    const uint4* phih = (const uint4*)g_phih;
    float acc[8];
#pragma unroll
    for (int q = 0; q < 8; q++) acc[q] = 0.f;
#pragma unroll 2
    for (int i = 0; i < cnt; i++) {
        int2 rec = lst[i];
        float t = __int_as_float(rec.y);
        int i0 = (int)t;
        float f = t - (float)i0;
        uint4 xa = tabl[(size_t)i0 * 32 + lane];
        uint4 xb = tabl[(size_t)(i0 + 1) * 32 + lane];
        uint4 pp = phih[(size_t)rec.x * 32 + lane];
        const __half2* ha = (const __half2*)&xa;
        const __half2* hb = (const __half2*)&xb;
        const __half2* hp = (const __half2*)&pp;
#pragma unroll
        for (int q = 0; q < 4; q++) {
            float2 a0 = __half22float2(ha[q]);
            float2 b0 = __half22float2(hb[q]);
            float2 p0 = __half22float2(hp[q]);
            float f0 = fmaf(f, b0.x - a0.x, a0.x);
            float f1 = fmaf(f, b0.y - a0.y, a0.y);
            acc[q * 2 + 0] = fmaf(f0, p0.x, acc[q * 2 + 0]);
            acc[q * 2 + 1] = fmaf(f1, p0.y, acc[q * 2 + 1]);
        }
    }
    float4* ag = (float4*)(g_agg + (size_t)a * D_C) + lane * 2;
    ag[0] = make_float4(acc[0], acc[1], acc[2], acc[3]);
    ag[1] = make_float4(acc[4], acc[5], acc[6], acc[7]);
    uint4 h, l2;
    split2(acc[0], acc[1], h.x, l2.x);
    split2(acc[2], acc[3], h.y, l2.y);
    split2(acc[4], acc[5], h.z, l2.z);
    split2(acc[6], acc[7], h.w, l2.w);
    ((uint4*)(g_as_h + (size_t)a * D_C))[lane] = h;
    ((uint4*)(g_as_l + (size_t)a * D_C))[lane] = l2;
}

// Overflow edges (expected count 0): atomic add on top of gather's stores.
__global__ void ovf_k(int l) {
    int w = threadIdx.x >> 5, lane = threadIdx.x & 31;
    int n = g_ovf_cnt;
    if (n > OVFCAP) n = OVFCAP;
    const uint4* tabl = (const uint4*)g_tabh[l];
    const uint4* phih = (const uint4*)g_phih;
    for (int i = w; i < n; i += 8) {
        int4 rec = g_ovf[i];
        float t = __int_as_float(rec.z);
        int i0 = (int)t;
        float f = t - (float)i0;
        uint4 xa = tabl[(size_t)i0 * 32 + lane];
        uint4 xb = tabl[(size_t)(i0 + 1) * 32 + lane];
        uint4 pp = phih[(size_t)rec.y * 32 + lane];
        const __half2* ha = (const __half2*)&xa;
        const __half2* hb = (const __half2*)&xb;
        const __half2* hp = (const __half2*)&pp;
        float v[8];
#pragma unroll
        for (int q = 0; q < 4; q++) {
            float2 a0 = __half22float2(ha[q]);
            float2 b0 = __half22float2(hb[q]);
            float2 p0 = __half22float2(hp[q]);
            v[q * 2 + 0] = fmaf(f, b0.x - a0.x, a0.x) * p0.x;
            v[q * 2 + 1] = fmaf(f, b0.y - a0.y, a0.y) * p0.y;
        }
        float* ag = g_agg + (size_t)rec.x * D_C + lane * 8;
        asm volatile("red.global.add.v4.f32 [%0], {%1, %2, %3, %4};"
                     :: "l"(ag), "f"(v[0]), "f"(v[1]), "f"(v[2]), "f"(v[3]) : "memory");
        asm volatile("red.global.add.v4.f32 [%0], {%1, %2, %3, %4};"
                     :: "l"(ag + 4), "f"(v[4]), "f"(v[5]), "f"(v[6]), "f"(v[7]) : "memory");
    }
}

// Re-split atoms touched by overflow (no-op when g_ovf_cnt == 0).
__global__ void fixup_k() {
    int w = threadIdx.x >> 5, lane = threadIdx.x & 31;
    int n = g_ovf_cnt;
    if (n > OVFCAP) n = OVFCAP;
    for (int i = w; i < n; i += 8) {
        int a = g_ovf[i].x;
        const float4* ar = (const float4*)(g_agg + (size_t)a * D_C);
        float4 v0 = ar[lane * 2], v1 = ar[lane * 2 + 1];
        uint4 h, l2;
        split2(v0.x, v0.y, h.x, l2.x);
        split2(v0.z, v0.w, h.y, l2.y);
        split2(v1.x, v1.y, h.z, l2.z);
        split2(v1.z, v1.w, h.w, l2.w);
        ((uint4*)(g_as_h + (size_t)a * D_C))[lane] = h;
        ((uint4*)(g_as_l + (size_t)a * D_C))[lane] = l2;
    }
}

// ---------------------------------------------------------------------------
// cp.async double-buffered mma.sync bf16 split-3 GEMM: C[51200,256] = A@W.
//   Grid (400, 2): CTA tile 128x128, 8 warps (2x4), K chunked by 64; two
//   64KB SMEM stages; loads of chunk c+1 overlap MMAs of chunk c.
// MODE 0: PhiH = half(D + bias)                (phi, fp16 out)
// MODE 1: splits(ssp(D + bias)) -> Oh/Ol       (hidden)
// MODE 2: Cout = Cin + D + bias, also splits   (residual)
// ---------------------------------------------------------------------------
#define STG_SZ 65536
#define SMEM_DYN (2 * STG_SZ)

__device__ __forceinline__ void cp_tile(const __nv_bfloat16* __restrict__ src,
                                        int k0, uint32_t dst, int t) {
#pragma unroll
    for (int u = t; u < 1024; u += 256) {
        int r = u >> 3, c = u & 7;
        const void* g = src + (size_t)r * 256 + k0 + c * 8;
        uint32_t d = dst + swz((uint32_t)(r * 128 + c * 16));
        asm volatile("cp.async.cg.shared.global [%0], [%1], 16;" :: "r"(d), "l"(g));
    }
}

template <int MODE>
__global__ __launch_bounds__(256) void bmma_k(
    const __nv_bfloat16* __restrict__ Ah, const __nv_bfloat16* __restrict__ Al,
    const __nv_bfloat16* __restrict__ Bh, const __nv_bfloat16* __restrict__ Bl,
    const float* __restrict__ bias, const float* __restrict__ Cin,
    float* __restrict__ Cout, __nv_bfloat16* __restrict__ Oh,
    __nv_bfloat16* __restrict__ Ol, __half* __restrict__ PhiH) {
    extern __shared__ char smem[];
    const int t = threadIdx.x, wid = t >> 5, lane = t & 31;
    const int wm = wid & 1, wn = wid >> 1;  // warp grid 2(M) x 4(N)
    const int m0 = blockIdx.x * 128, n0 = blockIdx.y * 128;

    const uint32_t sb = smem_u32(smem);
    const __nv_bfloat16* Ahb = Ah + (size_t)m0 * 256;
    const __nv_bfloat16* Alb = Al + (size_t)m0 * 256;
    const __nv_bfloat16* Bhb = Bh + (size_t)n0 * 256;
    const __nv_bfloat16* Blb = Bl + (size_t)n0 * 256;

    float acc[4][4][4];
#pragma unroll
    for (int i = 0; i < 4; i++)
#pragma unroll
        for (int j = 0; j < 4; j++)
#pragma unroll
            for (int q = 0; q < 4; q++) acc[i][j][q] = 0.f;

    const int lrow = lane & 15;
    const int lkb = (lane >> 4) << 4;

    auto issue = [&](int c) {
        uint32_t st = sb + (uint32_t)(c & 1) * STG_SZ;
        int k0 = c * 64;
        cp_tile(Ahb, k0, st + 0, t);
        cp_tile(Alb, k0, st + 16384, t);
        cp_tile(Bhb, k0, st + 32768, t);
        cp_tile(Blb, k0, st + 49152, t);
        asm volatile("cp.async.commit_group;" ::: "memory");
    };

    issue(0);
    for (int c = 0; c < 4; c++) {
        if (c < 3) {
            issue(c + 1);
            asm volatile("cp.async.wait_group 1;" ::: "memory");
        } else {
            asm volatile("cp.async.wait_group 0;" ::: "memory");
        }
        __syncthreads();
        uint32_t st = sb + (uint32_t)(c & 1) * STG_SZ;
#pragma unroll
        for (int k16 = 0; k16 < 4; k16++) {
            int kb = k16 * 32 + lkb;
            uint32_t bh[4][2], bl[4][2];
#pragma unroll
            for (int p = 0; p < 2; p++) {
                uint32_t off = swz((uint32_t)((wn * 32 + p * 16 + lrow) * 128 + kb));
                uint32_t r0, r1, r2, r3;
                ldmx4(st + 32768 + off, r0, r1, r2, r3);
                bh[p * 2 + 0][0] = r0; bh[p * 2 + 1][0] = r1;
                bh[p * 2 + 0][1] = r2; bh[p * 2 + 1][1] = r3;
                ldmx4(st + 49152 + off, r0, r1, r2, r3);
                bl[p * 2 + 0][0] = r0; bl[p * 2 + 1][0] = r1;
                bl[p * 2 + 0][1] = r2; bl[p * 2 + 1][1] = r3;
            }
#pragma unroll
            for (int mt = 0; mt < 4; mt++) {
                uint32_t off = swz((uint32_t)((wm * 64 + mt * 16 + lrow) * 128 + kb));
                uint32_t ah[4], al[4];
                ldmx4(st + 0 + off, ah[0], ah[1], ah[2], ah[3]);
                ldmx4(st + 16384 + off, al[0], al[1], al[2], al[3]);
#pragma unroll
                for (int nt = 0; nt < 4; nt++) {
                    mma16816(acc[mt][nt], ah, bh[nt]);
                    mma16816(acc[mt][nt], ah, bl[nt]);
                    mma16816(acc[mt][nt], al, bh[nt]);
                }
            }
        }
        __syncthreads();
    }

    const int qr = lane >> 2, qc = (lane & 3) * 2;
#pragma unroll
    for (int mt = 0; mt < 4; mt++) {
#pragma unroll
        for (int half = 0; half < 2; half++) {
            int r = m0 + wm * 64 + mt * 16 + qr + half * 8;
#pragma unroll
            for (int nt = 0; nt < 4; nt++) {
                int cc = n0 + wn * 32 + nt * 8 + qc;
                float v0 = acc[mt][nt][half * 2 + 0] + bias[cc];
                float v1 = acc[mt][nt][half * 2 + 1] + bias[cc + 1];
                if (MODE == 0) {
                    __half2 hv = __floats2half2_rn(v0, v1);
                    *(uint32_t*)(PhiH + (size_t)r * 256 + cc) =
                        *reinterpret_cast<uint32_t*>(&hv);
                }
                if (MODE == 1) { v0 = sspf(v0); v1 = sspf(v1); }
                if (MODE == 2) {
                    float2 ci = *(const float2*)(Cin + (size_t)r * 256 + cc);
                    v0 += ci.x; v1 += ci.y;
                    *(float2*)(Cout + (size_t)r * 256 + cc) = make_float2(v0, v1);
                }
                if (MODE != 0) {
                    uint32_t h, l;
                    split2(v0, v1, h, l);
                    *(uint32_t*)(Oh + (size_t)r * 256 + cc) = h;
                    *(uint32_t*)(Ol + (size_t)r * 256 + cc) = l;
                }
            }
        }
    }
}

// ---------------------------------------------------------------------------
// Readout tail (tiny)
// ---------------------------------------------------------------------------
__global__ void conf_sum_k() {
    int row = blockIdx.x, t = threadIdx.x;
    float s = 0.f;
#pragma unroll
    for (int i = 0; i < MOLSZ; i++) s += g_r[(row * MOLSZ + i) * D_C + t];
    g_cs[row * D_C + t] = s;
}

__global__ void mlp1_k(const float* __restrict__ mW1, const float* __restrict__ mb1) {
    __shared__ float s[D_C];
    int row = blockIdx.x, t = threadIdx.x;
    if (t < D_C) s[t] = g_cs[row * D_C + t];
    __syncthreads();
    float a = mb1[t];
    for (int k = 0; k < D_C; k++) a += s[k] * mW1[k * 384 + t];
    g_h1[row * 384 + t] = sspf(a);
}

__global__ void mlp2_k(const float* __restrict__ mW2, const float* __restrict__ mb2) {
    __shared__ float s[384];
    int row = blockIdx.x, t = threadIdx.x;
    if (t < 384) s[t] = g_h1[row * 384 + t];
    __syncthreads();
    float a = mb2[t];
    for (int k = 0; k < 384; k++) a += s[k] * mW2[k * 512 + t];
    g_hh[row * 512 + t] = a;
}

__global__ void fp_k(const float* __restrict__ w) {
    int m = blockIdx.x, t = threadIdx.x;
    float a = 0.f;
#pragma unroll
    for (int c = 0; c < NCONFS; c++)
        a += w[m * NCONFS + c] * g_hh[(m * NCONFS + c) * 512 + t];
    g_fp[m * 512 + t] = a;
}

__global__ void readout_k(const float* __restrict__ rW1, const float* __restrict__ rb1,
                          const float* __restrict__ rW2, const float* __restrict__ rb2,
                          float* __restrict__ out) {
    __shared__ float s[512];
    __shared__ float red[256];
    int m = blockIdx.x, t = threadIdx.x;
    s[t] = g_fp[m * 512 + t];
    s[t + 256] = g_fp[m * 512 + 256 + t];
    __syncthreads();
    float a = rb1[t];
    for (int j = 0; j < 512; j++) a += s[j] * rW1[j * D_C + t];
    red[t] = sspf(a) * rW2[t];
    __syncthreads();
    for (int st = 128; st > 0; st >>= 1) {
        if (t < st) red[t] += red[t + st];
        __syncthreads();
    }
    if (t == 0) out[m] = red[0] + rb2[0];
}

// ---------------------------------------------------------------------------
extern "C" void kernel_launch(void* const* d_in, const int* in_sizes, int n_in,
                              void* d_out, int out_size) {
    const float* nxyz    = (const float*)d_in[0];
    const float* weights = (const float*)d_in[1];
    const float* emb     = (const float*)d_in[2];
    const float* Wm      = (const float*)d_in[3];
    const float* bm      = (const float*)d_in[4];
    const float* Wf1     = (const float*)d_in[5];
    const float* bf1     = (const float*)d_in[6];
    const float* Wf2     = (const float*)d_in[7];
    const float* bf2     = (const float*)d_in[8];
    const float* Wo1     = (const float*)d_in[9];
    const float* bo1     = (const float*)d_in[10];
    const float* Wo2     = (const float*)d_in[11];
    const float* bo2     = (const float*)d_in[12];
    const float* mW1     = (const float*)d_in[13];
    const float* mb1     = (const float*)d_in[14];
    const float* mW2     = (const float*)d_in[15];
    const float* mb2     = (const float*)d_in[16];
    const float* rW1     = (const float*)d_in[17];
    const float* rb1     = (const float*)d_in[18];
    const float* rW2     = (const float*)d_in[19];
    const float* rb2     = (const float*)d_in[20];
    const int*   z       = (const int*)d_in[21];
    const int2*  nbr     = (const int2*)d_in[22];

    float *p_r;
    __half *p_phih;
    __nv_bfloat16 *p_rsh, *p_rsl, *p_ash, *p_asl, *p_hsh, *p_hsl, *p_wth, *p_wtl;
    cudaGetSymbolAddress((void**)&p_r, g_r);
    cudaGetSymbolAddress((void**)&p_phih, g_phih);
    cudaGetSymbolAddress((void**)&p_rsh, g_rs_h);
    cudaGetSymbolAddress((void**)&p_rsl, g_rs_l);
    cudaGetSymbolAddress((void**)&p_ash, g_as_h);
    cudaGetSymbolAddress((void**)&p_asl, g_as_l);
    cudaGetSymbolAddress((void**)&p_hsh, g_hs_h);
    cudaGetSymbolAddress((void**)&p_hsl, g_hs_l);
    cudaGetSymbolAddress((void**)&p_wth, g_wt_h);
    cudaGetSymbolAddress((void**)&p_wtl, g_wt_l);

    cudaFuncSetAttribute(bmma_k<0>, cudaFuncAttributeMaxDynamicSharedMemorySize, SMEM_DYN);
    cudaFuncSetAttribute(bmma_k<1>, cudaFuncAttributeMaxDynamicSharedMemorySize, SMEM_DYN);
    cudaFuncSetAttribute(bmma_k<2>, cudaFuncAttributeMaxDynamicSharedMemorySize, SMEM_DYN);

    zero_cnt_k<<<(N_ATOMS_C + 255) / 256, 256>>>();
    scatter_k<<<N_EDGES_C / 256, 256>>>((const float4*)nxyz, nbr);
    gather_emb_k<<<(N_ATOMS_C * 64) / 256, 256>>>((const float4*)emb, z);
    conv_w_k<<<(9 * 65536) / 256, 256>>>(Wm, Wo1, Wo2);
    build_tab_k<<<dim3(NTAB / 32, L_C), 256>>>(Wf1, bf1, Wf2, bf2);

    dim3 gg(N_ATOMS_C / 128, 2);  // (400, 2)
    for (int l = 0; l < L_C; l++) {
        int s0 = (l * 3 + 0) * 65536, s1 = (l * 3 + 1) * 65536, s2 = (l * 3 + 2) * 65536;
        bmma_k<0><<<gg, 256, SMEM_DYN>>>(p_rsh, p_rsl, p_wth + s0, p_wtl + s0,
                                         bm + l * D_C, nullptr, nullptr, nullptr, nullptr,
                                         p_phih);
        gather_k<<<N_ATOMS_C / 8, 256>>>(l);
        ovf_k<<<1, 256>>>(l);
        fixup_k<<<1, 256>>>();
        bmma_k<1><<<gg, 256, SMEM_DYN>>>(p_ash, p_asl, p_wth + s1, p_wtl + s1,
                                         bo1 + l * D_C, nullptr, nullptr, p_hsh, p_hsl,
                                         nullptr);
        bmma_k<2><<<gg, 256, SMEM_DYN>>>(p_hsh, p_hsl, p_wth + s2, p_wtl + s2,
                                         bo2 + l * D_C, p_r, p_r, p_rsh, p_rsl,
                                         nullptr);
    }

    conf_sum_k<<<NMOLS * NCONFS, 256>>>();
    mlp1_k<<<NMOLS * NCONFS, 384>>>(mW1, mb1);
    mlp2_k<<<NMOLS * NCONFS, 512>>>(mW2, mb2);
    fp_k<<<NMOLS, 512>>>(weights);
    readout_k<<<NMOLS, 256>>>(rW1, rb1, rW2, rb2, (float*)d_out);
}